// round 14
// baseline (speedup 1.0000x reference)
#include <cuda_runtime.h>
#include <math.h>

#define T_  512
#define B_  64
#define E_  256
#define H_  256
#define TB_ (T_ * B_)          // 32768
#define CLU 8                  // CTAs per cluster
#define BGR 8                  // batch elements per cluster

// ---------------- static device scratch ----------------
__device__ float g_Q  [TB_ * E_];
__device__ float g_K  [TB_ * E_];
__device__ float g_S  [B_ * T_ * T_];
__device__ float g_CTX[TB_ * E_];
__device__ float g_PRE[(long)TB_ * 4 * H_];
__device__ float g_Wall [512 * 1024];      // packed [Wf|Wi|Wu|Wo] as (512, 1024)
__device__ float g_Wfold[512 * 1024];      // rows 0..255 = Wx; rows 256..511 = Wc@Wh
__device__ float g_ball [1024];
__device__ float g_bfold[1024];            // bc@Wh + b
// recurrent W pre-packed as exact MMA A-fragments:
// [rank][warp(8)][ks(16)][lane(32)][8 u32: 4 hi + 4 lo]
__device__ unsigned g_WAfrag[CLU * 8 * 16 * 32 * 8];

// ---------------- bf16 2-split helpers ----------------
__device__ __forceinline__ void split_bf2(float e, float o, unsigned& hi, unsigned& lo)
{
    unsigned h;
    asm("cvt.rn.bf16x2.f32 %0, %1, %2;" : "=r"(h) : "f"(o), "f"(e));
    float eh = __uint_as_float(h << 16);
    float oh = __uint_as_float(h & 0xffff0000u);
    unsigned l;
    asm("cvt.rn.bf16x2.f32 %0, %1, %2;" : "=r"(l) : "f"(o - oh), "f"(e - eh));
    hi = h; lo = l;
}

#define MMA_BF16(c, a, b)                                                          \
    asm volatile("mma.sync.aligned.m16n8k16.row.col.f32.bf16.bf16.f32 "            \
                 "{%0,%1,%2,%3},{%4,%5,%6,%7},{%8,%9},{%0,%1,%2,%3};"              \
                 : "+f"(c[0]), "+f"(c[1]), "+f"(c[2]), "+f"(c[3])                  \
                 : "r"(a[0]), "r"(a[1]), "r"(a[2]), "r"(a[3]),                     \
                   "r"(b[0]), "r"(b[1]))

// ---------------- tensor-core bf16 GEMM, 128x128x16 tile, 3x split, occ 2 ----
// (exact proven R8/R12 version)
template<bool NT, bool BIAS, bool CONCAT>
__global__ void __launch_bounds__(256, 2) gemm_tc(
    const float* __restrict__ A, const float* __restrict__ A2,
    const float* __restrict__ B, float* __restrict__ C,
    const float* __restrict__ bias,
    int M, int N, int K, int lda, int ldb, int ldc,
    long sA, long sB, long sC)
{
    A += (long)blockIdx.z * sA;
    B += (long)blockIdx.z * sB;
    C += (long)blockIdx.z * sC;

    __shared__ unsigned As_hi[8][136], As_lo[8][136];
    __shared__ unsigned Bs_hi[8][136], Bs_lo[8][136];

    const int tid  = threadIdx.x;
    const int lane = tid & 31;
    const int warp = tid >> 5;
    const int m0 = blockIdx.y * 128;
    const int n0 = blockIdx.x * 128;
    const int wm = (warp >> 2) * 64;
    const int wn = (warp & 3) * 32;
    const int gq = lane >> 2;
    const int tg = lane & 3;

    const int ar = tid & 127;
    const int aq = (tid >> 7) * 4;
    const int bkr = tid >> 5;
    const int bn  = (tid & 31) * 4;
    const int bn_t = tid & 127;
    const int bq   = (tid >> 7) * 4;

    float acc[4][4][4];
    #pragma unroll
    for (int i = 0; i < 4; ++i)
        #pragma unroll
        for (int j = 0; j < 4; ++j)
            #pragma unroll
            for (int q = 0; q < 4; ++q) acc[i][j][q] = 0.f;

    float4 va0, va1, vb0, vb1;
    auto load_tile = [&](int k0) {
        const float* Ab = A;
        int kc = k0;
        if (CONCAT) { if (k0 >= 256) { Ab = A2; kc = k0 - 256; } }
        va0 = *(const float4*)(Ab + (long)(m0 + ar) * lda + kc + aq);
        va1 = *(const float4*)(Ab + (long)(m0 + ar) * lda + kc + aq + 8);
        if (NT) {
            vb0 = *(const float4*)(B + (long)(n0 + bn_t) * ldb + k0 + bq);
            vb1 = *(const float4*)(B + (long)(n0 + bn_t) * ldb + k0 + bq + 8);
        } else {
            vb0 = *(const float4*)(B + (long)(k0 + 2 * bkr) * ldb + n0 + bn);
            vb1 = *(const float4*)(B + (long)(k0 + 2 * bkr + 1) * ldb + n0 + bn);
        }
    };

    load_tile(0);

    for (int k0 = 0; k0 < K; k0 += 16) {
        __syncthreads();
        {
            int kp = aq >> 1;
            split_bf2(va0.x, va0.y, As_hi[kp    ][ar], As_lo[kp    ][ar]);
            split_bf2(va0.z, va0.w, As_hi[kp + 1][ar], As_lo[kp + 1][ar]);
            split_bf2(va1.x, va1.y, As_hi[kp + 4][ar], As_lo[kp + 4][ar]);
            split_bf2(va1.z, va1.w, As_hi[kp + 5][ar], As_lo[kp + 5][ar]);
            if (NT) {
                int bp = bq >> 1;
                split_bf2(vb0.x, vb0.y, Bs_hi[bp    ][bn_t], Bs_lo[bp    ][bn_t]);
                split_bf2(vb0.z, vb0.w, Bs_hi[bp + 1][bn_t], Bs_lo[bp + 1][bn_t]);
                split_bf2(vb1.x, vb1.y, Bs_hi[bp + 4][bn_t], Bs_lo[bp + 4][bn_t]);
                split_bf2(vb1.z, vb1.w, Bs_hi[bp + 5][bn_t], Bs_lo[bp + 5][bn_t]);
            } else {
                uint4 h4, l4;
                split_bf2(vb0.x, vb1.x, h4.x, l4.x);
                split_bf2(vb0.y, vb1.y, h4.y, l4.y);
                split_bf2(vb0.z, vb1.z, h4.z, l4.z);
                split_bf2(vb0.w, vb1.w, h4.w, l4.w);
                *(uint4*)&Bs_hi[bkr][bn] = h4;
                *(uint4*)&Bs_lo[bkr][bn] = l4;
            }
        }
        __syncthreads();

        int kn = (k0 + 16 < K) ? k0 + 16 : k0;
        load_tile(kn);

        unsigned ah[4][4], al[4][4], bh[4][2], bl[4][2];
        #pragma unroll
        for (int i = 0; i < 4; ++i) {
            int r = wm + i * 16 + gq;
            ah[i][0] = As_hi[tg    ][r];
            ah[i][1] = As_hi[tg    ][r + 8];
            ah[i][2] = As_hi[tg + 4][r];
            ah[i][3] = As_hi[tg + 4][r + 8];
            al[i][0] = As_lo[tg    ][r];
            al[i][1] = As_lo[tg    ][r + 8];
            al[i][2] = As_lo[tg + 4][r];
            al[i][3] = As_lo[tg + 4][r + 8];
        }
        #pragma unroll
        for (int j = 0; j < 4; ++j) {
            int n = wn + j * 8 + gq;
            bh[j][0] = Bs_hi[tg    ][n];
            bh[j][1] = Bs_hi[tg + 4][n];
            bl[j][0] = Bs_lo[tg    ][n];
            bl[j][1] = Bs_lo[tg + 4][n];
        }
        #pragma unroll
        for (int i = 0; i < 4; ++i)
            #pragma unroll
            for (int j = 0; j < 4; ++j) {
                MMA_BF16(acc[i][j], ah[i], bh[j]);
                MMA_BF16(acc[i][j], al[i], bh[j]);
                MMA_BF16(acc[i][j], ah[i], bl[j]);
            }
    }

    #pragma unroll
    for (int i = 0; i < 4; ++i)
        #pragma unroll
        for (int j = 0; j < 4; ++j) {
            int m = m0 + wm + i * 16 + gq;
            int n = n0 + wn + j * 8 + 2 * tg;
            float2 v0 = make_float2(acc[i][j][0], acc[i][j][1]);
            float2 v1 = make_float2(acc[i][j][2], acc[i][j][3]);
            if (BIAS) {
                float b0 = bias[n], b1 = bias[n + 1];
                v0.x += b0; v0.y += b1;
                v1.x += b0; v1.y += b1;
            }
            *(float2*)(C + (long)m * ldc + n)       = v0;
            *(float2*)(C + (long)(m + 8) * ldc + n) = v1;
        }
}

// ---------------- softmax over rows of length 512 ----------
__global__ void __launch_bounds__(128) softmax_k(float* __restrict__ S)
{
    float* p = S + (long)blockIdx.x * 512;
    int tid = threadIdx.x;
    float v[4];
    float m = -1e30f;
    #pragma unroll
    for (int i = 0; i < 4; ++i) { v[i] = p[tid + 128 * i] * 0.0625f; m = fmaxf(m, v[i]); }
    __shared__ float red[128];
    red[tid] = m; __syncthreads();
    for (int s = 64; s > 0; s >>= 1) { if (tid < s) red[tid] = fmaxf(red[tid], red[tid + s]); __syncthreads(); }
    m = red[0]; __syncthreads();
    float sum = 0.f;
    #pragma unroll
    for (int i = 0; i < 4; ++i) { v[i] = __expf(v[i] - m); sum += v[i]; }
    red[tid] = sum; __syncthreads();
    for (int s = 64; s > 0; s >>= 1) { if (tid < s) red[tid] += red[tid + s]; __syncthreads(); }
    float inv = 1.f / red[0];
    #pragma unroll
    for (int i = 0; i < 4; ++i) p[tid + 128 * i] = v[i] * inv;
}

// ---------------- pack weights ----------------
// A-fragment pack: value at (rank, w, ks, lane, q):
//   gq=lane>>2, tg=lane&3, kpabs = ks*8+tg + ((q&2)?4:0)
//   row c = w*16 + gq + ((q&1)?8:0)  ->  g=(gq>>2)+2*(q&1)(+..), jl=w*4+(gq&3)
//   value = (q<4 ? hi : lo) of split(W[(E+2kp)*H+j], W[(E+2kp+1)*H+j])
__global__ void pack_init_k(const float* __restrict__ Wf, const float* __restrict__ Wi,
                            const float* __restrict__ Wu, const float* __restrict__ Wo,
                            const float* __restrict__ bf, const float* __restrict__ bi,
                            const float* __restrict__ bu, const float* __restrict__ bo)
{
    int idx = blockIdx.x * blockDim.x + threadIdx.x;
    int nt = gridDim.x * blockDim.x;
    for (int i = idx; i < CLU * 8 * 16 * 32 * 8; i += nt) {
        int rank = i >> 15;
        int rem  = i & 32767;
        int w    = rem >> 12;
        int ks   = (rem >> 8) & 15;
        int lane = (rem >> 3) & 31;
        int q    = rem & 7;
        int gq = lane >> 2, tg = lane & 3;
        int kpabs = ks * 8 + tg + ((q & 2) ? 4 : 0);
        int c     = w * 16 + gq + ((q & 1) ? 8 : 0);
        int g  = (c >> 2) & 3;
        int jl = ((c >> 4) << 2) + (c & 3);
        int j  = rank * 32 + jl;
        const float* W = (g == 0) ? Wf : (g == 1) ? Wi : (g == 2) ? Wu : Wo;
        float w0 = W[(E_ + 2 * kpabs) * H_ + j];
        float w1 = W[(E_ + 2 * kpabs + 1) * H_ + j];
        unsigned hi, lo;
        split_bf2(w0, w1, hi, lo);
        g_WAfrag[i] = (q < 4) ? hi : lo;
    }
    for (int i = idx; i < 512 * 1024; i += nt) {
        int k = i >> 10;
        int col = i & 1023;
        int g = col >> 8, j = col & 255;
        const float* W = (g == 0) ? Wf : (g == 1) ? Wi : (g == 2) ? Wu : Wo;
        float v = W[k * 256 + j];
        g_Wall[i] = v;
        if (i < 256 * 1024) g_Wfold[i] = v;
    }
    for (int i = idx; i < 1024; i += nt) {
        int g = i >> 8;
        const float* b = (g == 0) ? bf : (g == 1) ? bi : (g == 2) ? bu : bo;
        g_ball[i] = b[i & 255];
    }
}

// bfold[col] = ball[col] + sum_h bc[h] * Wall[256+h][col]
__global__ void __launch_bounds__(256) bias_fold_k(const float* __restrict__ bc)
{
    int col  = blockIdx.x * 8 + (threadIdx.x >> 5);
    int lane = threadIdx.x & 31;
    float s = 0.f;
    #pragma unroll
    for (int h = lane; h < 256; h += 32)
        s += bc[h] * g_Wall[(256 + h) * 1024 + col];
    #pragma unroll
    for (int o = 16; o > 0; o >>= 1)
        s += __shfl_xor_sync(0xffffffffu, s, o);
    if (lane == 0) g_bfold[col] = g_ball[col] + s;
}

__device__ __forceinline__ float sigf(float x)  { return 1.f / (1.f + __expf(-x)); }
__device__ __forceinline__ float tanhf_(float x){ return 2.f / (1.f + __expf(-2.f * x)) - 1.f; }

#define CARRIVE() asm volatile("barrier.cluster.arrive.aligned;" ::: "memory")
#define CWAIT()   asm volatile("barrier.cluster.wait.aligned;"   ::: "memory")

// ---------------- cluster LSTM recurrence: tensor-core mainloop ----------------
// Same structure as proven R13, but A fragments pre-packed: 2x LDS.128 per kstep
// (was 8x LDS.32 x2). Values bit-identical to R13.
__global__ void __launch_bounds__(256, 1) __cluster_dims__(CLU, 1, 1)
recur9_k(const float* __restrict__ PRE, float* __restrict__ out)
{
    extern __shared__ unsigned smu[];
    unsigned* wfrag = smu;                   // [8 w][16 ks][32 lane][8] = 32768 u32
    float* hbuf     = (float*)(smu + 32768); // [2 buf][256 k][12]

    const int tid  = threadIdx.x;
    const int lane = tid & 31;
    const int warp = tid >> 5;
    const int gq = lane >> 2;
    const int tg = lane & 3;
    unsigned rank;
    asm("mov.u32 %0, %%cluster_ctarank;" : "=r"(rank));
    const int bg0 = (blockIdx.x >> 3) * BGR;

    // preload this rank's fragment slice + zero h buffers
    {
        const uint4* src = (const uint4*)(g_WAfrag + (long)rank * 32768);
        uint4* dst = (uint4*)wfrag;
        for (int m = tid; m < 8192; m += 256) dst[m] = src[m];
        for (int m = tid; m < 6144; m += 256) hbuf[m] = 0.f;
    }

    // cell identity for this lane (same mapping as R13)
    const int jl    = warp * 4 + (gq & 3);
    const int jg    = rank * 32 + jl;
    const int b     = 2 * tg + (gq >> 2);
    const int bglob = bg0 + b;

    float creg = 0.f, hreg = 0.f;
    float p0, p1, p2, p3;
    {
        const float* pp = PRE + (long)bglob * 1024 + jg;
        p0 = pp[0]; p1 = pp[256]; p2 = pp[512]; p3 = pp[768];
    }

    const unsigned hb_u32 = (unsigned)__cvta_generic_to_shared(hbuf);
    const uint4* af = (const uint4*)wfrag + ((warp * 16) * 32 + lane) * 2;

    __syncthreads();
    CARRIVE(); CWAIT();

    for (int t = 0; t < T_; ++t) {
        const int buf = t & 1;
        const float* hp = hbuf + buf * 3072;

        float acc[4] = {0.f, 0.f, 0.f, 0.f};
        #pragma unroll
        for (int ks = 0; ks < 16; ++ks) {
            const int k0 = ks * 16 + tg * 2;
            float h00 = hp[(k0    ) * 12 + gq];
            float h01 = hp[(k0 + 1) * 12 + gq];
            float h10 = hp[(k0 + 8) * 12 + gq];
            float h11 = hp[(k0 + 9) * 12 + gq];
            unsigned b0h, b0l, b1h, b1l;
            split_bf2(h00, h01, b0h, b0l);
            split_bf2(h10, h11, b1h, b1l);
            uint4 AH = af[ks * 64];
            uint4 AL = af[ks * 64 + 1];
            unsigned avh[4] = {AH.x, AH.y, AH.z, AH.w};
            unsigned avl[4] = {AL.x, AL.y, AL.z, AL.w};
            unsigned bvh[2] = {b0h, b1h};
            unsigned bvl[2] = {b0l, b1l};
            MMA_BF16(acc, avh, bvh);
            MMA_BF16(acc, avl, bvh);
            MMA_BF16(acc, avh, bvl);
        }

        // pair gate owners: lane^16 flips gq bit2
        float r0 = __shfl_xor_sync(0xffffffffu, acc[0], 16);
        float r1 = __shfl_xor_sync(0xffffffffu, acc[1], 16);
        float r2 = __shfl_xor_sync(0xffffffffu, acc[2], 16);
        float r3 = __shfl_xor_sync(0xffffffffu, acc[3], 16);
        float s0, s1, s2, s3;
        if (gq < 4) { s0 = acc[0]; s1 = r0;     s2 = acc[2]; s3 = r2;     }
        else        { s0 = r1;     s1 = acc[1]; s2 = r3;     s3 = acc[3]; }

        float fg = sigf  (s0 + p0);
        float ig = sigf  (s1 + p1);
        float ug = tanhf_(s2 + p2);
        float og = sigf  (s3 + p3);
        creg = fg * creg + ig * ug;
        hreg = og * tanhf_(creg);
        out[((long)t * B_ + bglob) * H_ + jg] = hreg;

        // publish h to all cluster CTAs' hbuf[buf^1]
        unsigned laddr = hb_u32 + ((((buf ^ 1) * 256 + jg) * 12 + b) << 2);
        #pragma unroll
        for (int rr = 0; rr < CLU; ++rr) {
            unsigned ra;
            asm volatile("mapa.shared::cluster.u32 %0, %1, %2;"
                         : "=r"(ra) : "r"(laddr), "r"(rr));
            asm volatile("st.shared::cluster.f32 [%0], %1;"
                         :: "r"(ra), "f"(hreg) : "memory");
        }

        // prefetch next step's PRE
        int tn = (t < T_ - 1) ? t + 1 : t;
        const float* pq = PRE + ((long)tn * B_ + bglob) * 1024 + jg;
        p0 = pq[0]; p1 = pq[256]; p2 = pq[512]; p3 = pq[768];

        CARRIVE();
        CWAIT();
    }

    out[(long)TB_ * H_ + bglob * H_ + jg] = hreg;                 // hx
    out[(long)TB_ * H_ + (long)B_ * H_ + bglob * H_ + jg] = creg; // cx
}

// ---------------- launch ----------------
extern "C" void kernel_launch(void* const* d_in, const int* in_sizes, int n_in,
                              void* d_out, int out_size)
{
    const float* inputs = (const float*)d_in[0];
    const float* rot    = (const float*)d_in[1];
    const float* ent    = (const float*)d_in[2];
    const float* Wf = (const float*)d_in[3];  const float* bf = (const float*)d_in[4];
    const float* Wi = (const float*)d_in[5];  const float* bi = (const float*)d_in[6];
    const float* Wu = (const float*)d_in[7];  const float* bu = (const float*)d_in[8];
    const float* Wo = (const float*)d_in[9];  const float* bo = (const float*)d_in[10];
    const float* Wc = (const float*)d_in[11]; const float* bc = (const float*)d_in[12];
    float* out = (float*)d_out;

    float *Q, *K, *S, *CTX, *PRE, *Wall, *Wfold, *bfold;
    cudaGetSymbolAddress((void**)&Q,     g_Q);
    cudaGetSymbolAddress((void**)&K,     g_K);
    cudaGetSymbolAddress((void**)&S,     g_S);
    cudaGetSymbolAddress((void**)&CTX,   g_CTX);
    cudaGetSymbolAddress((void**)&PRE,   g_PRE);
    cudaGetSymbolAddress((void**)&Wall,  g_Wall);
    cudaGetSymbolAddress((void**)&Wfold, g_Wfold);
    cudaGetSymbolAddress((void**)&bfold, g_bfold);

    const int RSMEM = 32768 * 4 + 6144 * 4;   // 155648 B
    cudaFuncSetAttribute(recur9_k, cudaFuncAttributeMaxDynamicSharedMemorySize, RSMEM);

    pack_init_k<<<256, 256>>>(Wf, Wi, Wu, Wo, bf, bi, bu, bo);
    bias_fold_k<<<128, 256>>>(bc);

    // Wfold[256:512] = Wc @ Wall[256:512]
    gemm_tc<false, false, false><<<dim3(1024 / 128, 256 / 128, 1), 256>>>(
        Wc, nullptr, Wall + 256 * 1024, Wfold + 256 * 1024, nullptr,
        256, 1024, 256, 256, 1024, 1024, 0, 0, 0);

    // Q = X @ rot ; K = X @ ent
    gemm_tc<false, false, false><<<dim3(E_ / 128, TB_ / 128, 1), 256>>>(
        inputs, nullptr, rot, Q, nullptr, TB_, E_, E_, E_, E_, E_, 0, 0, 0);
    gemm_tc<false, false, false><<<dim3(E_ / 128, TB_ / 128, 1), 256>>>(
        inputs, nullptr, ent, K, nullptr, TB_, E_, E_, E_, E_, E_, 0, 0, 0);

    // scores_b = Q_b @ K_b^T
    gemm_tc<true, false, false><<<dim3(T_ / 128, T_ / 128, B_), 256>>>(
        Q, nullptr, K, S, nullptr, T_, T_, E_, B_ * E_, B_ * E_, T_,
        (long)E_, (long)E_, (long)T_ * T_);

    softmax_k<<<B_ * T_, 128>>>(S);

    // context_b = S_b @ X_b
    gemm_tc<false, false, false><<<dim3(E_ / 128, T_ / 128, B_), 256>>>(
        S, nullptr, inputs, CTX, nullptr, T_, E_, T_, T_, B_ * E_, B_ * E_,
        (long)T_ * T_, (long)E_, (long)E_);

    // PRE = [X | CTX] @ Wfold + bfold
    gemm_tc<false, true, true><<<dim3(1024 / 128, TB_ / 128, 1), 256>>>(
        inputs, CTX, Wfold, PRE, bfold, TB_, 1024, 512, E_, 1024, 1024, 0, 0, 0);

    recur9_k<<<64, 256, RSMEM>>>(PRE, out);
    (void)in_sizes; (void)n_in; (void)out_size;
}

// round 15
// speedup vs baseline: 1.1900x; 1.1900x over previous
#include <cuda_runtime.h>
#include <math.h>

#define T_  512
#define B_  64
#define E_  256
#define H_  256
#define TB_ (T_ * B_)          // 32768
#define CLU 8                  // CTAs per cluster
#define BGR 8                  // batch elements per cluster

// ---------------- static device scratch ----------------
__device__ float g_Q  [TB_ * E_];
__device__ float g_K  [TB_ * E_];
__device__ float g_S  [B_ * T_ * T_];
__device__ float g_CTX[TB_ * E_];
__device__ float g_PRE[(long)TB_ * 4 * H_];
__device__ float g_Wall [512 * 1024];      // packed [Wf|Wi|Wu|Wo] as (512, 1024)
__device__ float g_Wfold[512 * 1024];      // rows 0..255 = Wx; rows 256..511 = Wc@Wh
__device__ float g_ball [1024];
__device__ float g_bfold[1024];            // bc@Wh + b
// recurrent W for MMA (R13 layout): bf16 split pairs along k, [rank][c(128)][kp(140 pad)]
__device__ unsigned g_WAh[CLU * 128 * 140];
__device__ unsigned g_WAl[CLU * 128 * 140];

// ---------------- bf16 2-split helpers ----------------
__device__ __forceinline__ void split_bf2(float e, float o, unsigned& hi, unsigned& lo)
{
    unsigned h;
    asm("cvt.rn.bf16x2.f32 %0, %1, %2;" : "=r"(h) : "f"(o), "f"(e));
    float eh = __uint_as_float(h << 16);
    float oh = __uint_as_float(h & 0xffff0000u);
    unsigned l;
    asm("cvt.rn.bf16x2.f32 %0, %1, %2;" : "=r"(l) : "f"(o - oh), "f"(e - eh));
    hi = h; lo = l;
}

#define MMA_BF16(c, a, b)                                                          \
    asm volatile("mma.sync.aligned.m16n8k16.row.col.f32.bf16.bf16.f32 "            \
                 "{%0,%1,%2,%3},{%4,%5,%6,%7},{%8,%9},{%0,%1,%2,%3};"              \
                 : "+f"(c[0]), "+f"(c[1]), "+f"(c[2]), "+f"(c[3])                  \
                 : "r"(a[0]), "r"(a[1]), "r"(a[2]), "r"(a[3]),                     \
                   "r"(b[0]), "r"(b[1]))

// ---------------- tensor-core bf16 GEMM, 128x128x16 tile, 3x split, occ 2 ----
// (exact proven R8/R12 version)
template<bool NT, bool BIAS, bool CONCAT>
__global__ void __launch_bounds__(256, 2) gemm_tc(
    const float* __restrict__ A, const float* __restrict__ A2,
    const float* __restrict__ B, float* __restrict__ C,
    const float* __restrict__ bias,
    int M, int N, int K, int lda, int ldb, int ldc,
    long sA, long sB, long sC)
{
    A += (long)blockIdx.z * sA;
    B += (long)blockIdx.z * sB;
    C += (long)blockIdx.z * sC;

    __shared__ unsigned As_hi[8][136], As_lo[8][136];
    __shared__ unsigned Bs_hi[8][136], Bs_lo[8][136];

    const int tid  = threadIdx.x;
    const int lane = tid & 31;
    const int warp = tid >> 5;
    const int m0 = blockIdx.y * 128;
    const int n0 = blockIdx.x * 128;
    const int wm = (warp >> 2) * 64;
    const int wn = (warp & 3) * 32;
    const int gq = lane >> 2;
    const int tg = lane & 3;

    const int ar = tid & 127;
    const int aq = (tid >> 7) * 4;
    const int bkr = tid >> 5;
    const int bn  = (tid & 31) * 4;
    const int bn_t = tid & 127;
    const int bq   = (tid >> 7) * 4;

    float acc[4][4][4];
    #pragma unroll
    for (int i = 0; i < 4; ++i)
        #pragma unroll
        for (int j = 0; j < 4; ++j)
            #pragma unroll
            for (int q = 0; q < 4; ++q) acc[i][j][q] = 0.f;

    float4 va0, va1, vb0, vb1;
    auto load_tile = [&](int k0) {
        const float* Ab = A;
        int kc = k0;
        if (CONCAT) { if (k0 >= 256) { Ab = A2; kc = k0 - 256; } }
        va0 = *(const float4*)(Ab + (long)(m0 + ar) * lda + kc + aq);
        va1 = *(const float4*)(Ab + (long)(m0 + ar) * lda + kc + aq + 8);
        if (NT) {
            vb0 = *(const float4*)(B + (long)(n0 + bn_t) * ldb + k0 + bq);
            vb1 = *(const float4*)(B + (long)(n0 + bn_t) * ldb + k0 + bq + 8);
        } else {
            vb0 = *(const float4*)(B + (long)(k0 + 2 * bkr) * ldb + n0 + bn);
            vb1 = *(const float4*)(B + (long)(k0 + 2 * bkr + 1) * ldb + n0 + bn);
        }
    };

    load_tile(0);

    for (int k0 = 0; k0 < K; k0 += 16) {
        __syncthreads();
        {
            int kp = aq >> 1;
            split_bf2(va0.x, va0.y, As_hi[kp    ][ar], As_lo[kp    ][ar]);
            split_bf2(va0.z, va0.w, As_hi[kp + 1][ar], As_lo[kp + 1][ar]);
            split_bf2(va1.x, va1.y, As_hi[kp + 4][ar], As_lo[kp + 4][ar]);
            split_bf2(va1.z, va1.w, As_hi[kp + 5][ar], As_lo[kp + 5][ar]);
            if (NT) {
                int bp = bq >> 1;
                split_bf2(vb0.x, vb0.y, Bs_hi[bp    ][bn_t], Bs_lo[bp    ][bn_t]);
                split_bf2(vb0.z, vb0.w, Bs_hi[bp + 1][bn_t], Bs_lo[bp + 1][bn_t]);
                split_bf2(vb1.x, vb1.y, Bs_hi[bp + 4][bn_t], Bs_lo[bp + 4][bn_t]);
                split_bf2(vb1.z, vb1.w, Bs_hi[bp + 5][bn_t], Bs_lo[bp + 5][bn_t]);
            } else {
                uint4 h4, l4;
                split_bf2(vb0.x, vb1.x, h4.x, l4.x);
                split_bf2(vb0.y, vb1.y, h4.y, l4.y);
                split_bf2(vb0.z, vb1.z, h4.z, l4.z);
                split_bf2(vb0.w, vb1.w, h4.w, l4.w);
                *(uint4*)&Bs_hi[bkr][bn] = h4;
                *(uint4*)&Bs_lo[bkr][bn] = l4;
            }
        }
        __syncthreads();

        int kn = (k0 + 16 < K) ? k0 + 16 : k0;
        load_tile(kn);

        unsigned ah[4][4], al[4][4], bh[4][2], bl[4][2];
        #pragma unroll
        for (int i = 0; i < 4; ++i) {
            int r = wm + i * 16 + gq;
            ah[i][0] = As_hi[tg    ][r];
            ah[i][1] = As_hi[tg    ][r + 8];
            ah[i][2] = As_hi[tg + 4][r];
            ah[i][3] = As_hi[tg + 4][r + 8];
            al[i][0] = As_lo[tg    ][r];
            al[i][1] = As_lo[tg    ][r + 8];
            al[i][2] = As_lo[tg + 4][r];
            al[i][3] = As_lo[tg + 4][r + 8];
        }
        #pragma unroll
        for (int j = 0; j < 4; ++j) {
            int n = wn + j * 8 + gq;
            bh[j][0] = Bs_hi[tg    ][n];
            bh[j][1] = Bs_hi[tg + 4][n];
            bl[j][0] = Bs_lo[tg    ][n];
            bl[j][1] = Bs_lo[tg + 4][n];
        }
        #pragma unroll
        for (int i = 0; i < 4; ++i)
            #pragma unroll
            for (int j = 0; j < 4; ++j) {
                MMA_BF16(acc[i][j], ah[i], bh[j]);
                MMA_BF16(acc[i][j], al[i], bh[j]);
                MMA_BF16(acc[i][j], ah[i], bl[j]);
            }
    }

    #pragma unroll
    for (int i = 0; i < 4; ++i)
        #pragma unroll
        for (int j = 0; j < 4; ++j) {
            int m = m0 + wm + i * 16 + gq;
            int n = n0 + wn + j * 8 + 2 * tg;
            float2 v0 = make_float2(acc[i][j][0], acc[i][j][1]);
            float2 v1 = make_float2(acc[i][j][2], acc[i][j][3]);
            if (BIAS) {
                float b0 = bias[n], b1 = bias[n + 1];
                v0.x += b0; v0.y += b1;
                v1.x += b0; v1.y += b1;
            }
            *(float2*)(C + (long)m * ldc + n)       = v0;
            *(float2*)(C + (long)(m + 8) * ldc + n) = v1;
        }
}

// ---------------- softmax over rows of length 512 ----------
__global__ void __launch_bounds__(128) softmax_k(float* __restrict__ S)
{
    float* p = S + (long)blockIdx.x * 512;
    int tid = threadIdx.x;
    float v[4];
    float m = -1e30f;
    #pragma unroll
    for (int i = 0; i < 4; ++i) { v[i] = p[tid + 128 * i] * 0.0625f; m = fmaxf(m, v[i]); }
    __shared__ float red[128];
    red[tid] = m; __syncthreads();
    for (int s = 64; s > 0; s >>= 1) { if (tid < s) red[tid] = fmaxf(red[tid], red[tid + s]); __syncthreads(); }
    m = red[0]; __syncthreads();
    float sum = 0.f;
    #pragma unroll
    for (int i = 0; i < 4; ++i) { v[i] = __expf(v[i] - m); sum += v[i]; }
    red[tid] = sum; __syncthreads();
    for (int s = 64; s > 0; s >>= 1) { if (tid < s) red[tid] += red[tid + s]; __syncthreads(); }
    float inv = 1.f / red[0];
    #pragma unroll
    for (int i = 0; i < 4; ++i) p[tid + 128 * i] = v[i] * inv;
}

// ---------------- pack weights (R13 layout) ----------------
// col mapping: warp w = c>>4, cl = c&15:  jl = w*4 + (cl&3), g = (cl>>2)&3
__global__ void pack_init_k(const float* __restrict__ Wf, const float* __restrict__ Wi,
                            const float* __restrict__ Wu, const float* __restrict__ Wo,
                            const float* __restrict__ bf, const float* __restrict__ bi,
                            const float* __restrict__ bu, const float* __restrict__ bo)
{
    int idx = blockIdx.x * blockDim.x + threadIdx.x;
    int nt = gridDim.x * blockDim.x;
    for (int i = idx; i < CLU * 128 * 128; i += nt) {
        int r   = i >> 14;
        int c   = (i >> 7) & 127;
        int kp  = i & 127;
        int jl  = ((c >> 4) << 2) + (c & 3);
        int g   = (c >> 2) & 3;
        int j   = r * 32 + jl;
        const float* W = (g == 0) ? Wf : (g == 1) ? Wi : (g == 2) ? Wu : Wo;
        float w0 = W[(E_ + 2 * kp) * H_ + j];
        float w1 = W[(E_ + 2 * kp + 1) * H_ + j];
        unsigned hi, lo;
        split_bf2(w0, w1, hi, lo);
        long o = (long)r * (128 * 140) + c * 140 + kp;
        g_WAh[o] = hi;
        g_WAl[o] = lo;
    }
    for (int i = idx; i < 512 * 1024; i += nt) {
        int k = i >> 10;
        int col = i & 1023;
        int g = col >> 8, j = col & 255;
        const float* W = (g == 0) ? Wf : (g == 1) ? Wi : (g == 2) ? Wu : Wo;
        float v = W[k * 256 + j];
        g_Wall[i] = v;
        if (i < 256 * 1024) g_Wfold[i] = v;
    }
    for (int i = idx; i < 1024; i += nt) {
        int g = i >> 8;
        const float* b = (g == 0) ? bf : (g == 1) ? bi : (g == 2) ? bu : bo;
        g_ball[i] = b[i & 255];
    }
}

// bfold[col] = ball[col] + sum_h bc[h] * Wall[256+h][col]
__global__ void __launch_bounds__(256) bias_fold_k(const float* __restrict__ bc)
{
    int col  = blockIdx.x * 8 + (threadIdx.x >> 5);
    int lane = threadIdx.x & 31;
    float s = 0.f;
    #pragma unroll
    for (int h = lane; h < 256; h += 32)
        s += bc[h] * g_Wall[(256 + h) * 1024 + col];
    #pragma unroll
    for (int o = 16; o > 0; o >>= 1)
        s += __shfl_xor_sync(0xffffffffu, s, o);
    if (lane == 0) g_bfold[col] = g_ball[col] + s;
}

__device__ __forceinline__ float sigf(float x)  { return 1.f / (1.f + __expf(-x)); }
__device__ __forceinline__ float tanhf_(float x){ return 2.f / (1.f + __expf(-2.f * x)) - 1.f; }

#define CARRIVE() asm volatile("barrier.cluster.arrive.aligned;" ::: "memory")
#define CWAIT()   asm volatile("barrier.cluster.wait.aligned;"   ::: "memory")

// ------------- cluster LSTM recurrence: W fragments REGISTER-RESIDENT ---------
// Same math/mapping as proven R13 recur8_k, but the 128 static Wh fragment words
// per lane are loaded ONCE from gmem into registers; mainloop has only h-loads,
// splits, and MMAs. smem = hbuf only (24KB).
__global__ void __launch_bounds__(256, 1) __cluster_dims__(CLU, 1, 1)
recur10_k(const float* __restrict__ PRE, float* __restrict__ out)
{
    extern __shared__ float hbuf[];          // [2 buf][256 k][12]

    const int tid  = threadIdx.x;
    const int lane = tid & 31;
    const int warp = tid >> 5;
    const int gq = lane >> 2;
    const int tg = lane & 3;
    unsigned rank;
    asm("mov.u32 %0, %%cluster_ctarank;" : "=r"(rank));
    const int bg0 = (blockIdx.x >> 3) * BGR;

    for (int m = tid; m < 6144; m += 256) hbuf[m] = 0.f;

    // load this lane's A fragments (R13 indices) into registers, once
    unsigned avh[16][4], avl[16][4];
    {
        const unsigned* wh0 = g_WAh + (long)rank * 17920 + (warp * 16 + gq) * 140;
        const unsigned* wh1 = g_WAh + (long)rank * 17920 + (warp * 16 + gq + 8) * 140;
        const unsigned* wl0 = g_WAl + (long)rank * 17920 + (warp * 16 + gq) * 140;
        const unsigned* wl1 = g_WAl + (long)rank * 17920 + (warp * 16 + gq + 8) * 140;
        #pragma unroll
        for (int ks = 0; ks < 16; ++ks) {
            const int kp = ks * 8 + tg;
            avh[ks][0] = wh0[kp];     avh[ks][1] = wh1[kp];
            avh[ks][2] = wh0[kp + 4]; avh[ks][3] = wh1[kp + 4];
            avl[ks][0] = wl0[kp];     avl[ks][1] = wl1[kp];
            avl[ks][2] = wl0[kp + 4]; avl[ks][3] = wl1[kp + 4];
        }
    }

    // cell identity for this lane (R13 mapping)
    const int jl    = warp * 4 + (gq & 3);
    const int jg    = rank * 32 + jl;
    const int b     = 2 * tg + (gq >> 2);
    const int bglob = bg0 + b;

    float creg = 0.f, hreg = 0.f;
    float p0, p1, p2, p3;
    {
        const float* pp = PRE + (long)bglob * 1024 + jg;
        p0 = pp[0]; p1 = pp[256]; p2 = pp[512]; p3 = pp[768];
    }

    const unsigned hb_u32 = (unsigned)__cvta_generic_to_shared(hbuf);

    __syncthreads();
    CARRIVE(); CWAIT();

    for (int t = 0; t < T_; ++t) {
        const int buf = t & 1;
        const float* hp = hbuf + buf * 3072;

        float acc[4] = {0.f, 0.f, 0.f, 0.f};
        #pragma unroll
        for (int ks = 0; ks < 16; ++ks) {
            const int k0 = ks * 16 + tg * 2;
            float h00 = hp[(k0    ) * 12 + gq];
            float h01 = hp[(k0 + 1) * 12 + gq];
            float h10 = hp[(k0 + 8) * 12 + gq];
            float h11 = hp[(k0 + 9) * 12 + gq];
            unsigned b0h, b0l, b1h, b1l;
            split_bf2(h00, h01, b0h, b0l);
            split_bf2(h10, h11, b1h, b1l);
            unsigned bvh[2] = {b0h, b1h};
            unsigned bvl[2] = {b0l, b1l};
            MMA_BF16(acc, avh[ks], bvh);
            MMA_BF16(acc, avl[ks], bvh);
            MMA_BF16(acc, avh[ks], bvl);
        }

        // pair gate owners: lane^16 flips gq bit2
        float r0 = __shfl_xor_sync(0xffffffffu, acc[0], 16);
        float r1 = __shfl_xor_sync(0xffffffffu, acc[1], 16);
        float r2 = __shfl_xor_sync(0xffffffffu, acc[2], 16);
        float r3 = __shfl_xor_sync(0xffffffffu, acc[3], 16);
        float s0, s1, s2, s3;
        if (gq < 4) { s0 = acc[0]; s1 = r0;     s2 = acc[2]; s3 = r2;     }
        else        { s0 = r1;     s1 = acc[1]; s2 = r3;     s3 = acc[3]; }

        float fg = sigf  (s0 + p0);
        float ig = sigf  (s1 + p1);
        float ug = tanhf_(s2 + p2);
        float og = sigf  (s3 + p3);
        creg = fg * creg + ig * ug;
        hreg = og * tanhf_(creg);
        out[((long)t * B_ + bglob) * H_ + jg] = hreg;

        // publish h to all cluster CTAs' hbuf[buf^1]
        unsigned laddr = hb_u32 + ((((buf ^ 1) * 256 + jg) * 12 + b) << 2);
        #pragma unroll
        for (int rr = 0; rr < CLU; ++rr) {
            unsigned ra;
            asm volatile("mapa.shared::cluster.u32 %0, %1, %2;"
                         : "=r"(ra) : "r"(laddr), "r"(rr));
            asm volatile("st.shared::cluster.f32 [%0], %1;"
                         :: "r"(ra), "f"(hreg) : "memory");
        }

        // prefetch next step's PRE
        int tn = (t < T_ - 1) ? t + 1 : t;
        const float* pq = PRE + ((long)tn * B_ + bglob) * 1024 + jg;
        p0 = pq[0]; p1 = pq[256]; p2 = pq[512]; p3 = pq[768];

        CARRIVE();
        CWAIT();
    }

    out[(long)TB_ * H_ + bglob * H_ + jg] = hreg;                 // hx
    out[(long)TB_ * H_ + (long)B_ * H_ + bglob * H_ + jg] = creg; // cx
}

// ---------------- launch ----------------
extern "C" void kernel_launch(void* const* d_in, const int* in_sizes, int n_in,
                              void* d_out, int out_size)
{
    const float* inputs = (const float*)d_in[0];
    const float* rot    = (const float*)d_in[1];
    const float* ent    = (const float*)d_in[2];
    const float* Wf = (const float*)d_in[3];  const float* bf = (const float*)d_in[4];
    const float* Wi = (const float*)d_in[5];  const float* bi = (const float*)d_in[6];
    const float* Wu = (const float*)d_in[7];  const float* bu = (const float*)d_in[8];
    const float* Wo = (const float*)d_in[9];  const float* bo = (const float*)d_in[10];
    const float* Wc = (const float*)d_in[11]; const float* bc = (const float*)d_in[12];
    float* out = (float*)d_out;

    float *Q, *K, *S, *CTX, *PRE, *Wall, *Wfold, *bfold;
    cudaGetSymbolAddress((void**)&Q,     g_Q);
    cudaGetSymbolAddress((void**)&K,     g_K);
    cudaGetSymbolAddress((void**)&S,     g_S);
    cudaGetSymbolAddress((void**)&CTX,   g_CTX);
    cudaGetSymbolAddress((void**)&PRE,   g_PRE);
    cudaGetSymbolAddress((void**)&Wall,  g_Wall);
    cudaGetSymbolAddress((void**)&Wfold, g_Wfold);
    cudaGetSymbolAddress((void**)&bfold, g_bfold);

    const int RSMEM = 6144 * 4;   // 24576 B (hbuf only)
    cudaFuncSetAttribute(recur10_k, cudaFuncAttributeMaxDynamicSharedMemorySize, RSMEM);

    pack_init_k<<<256, 256>>>(Wf, Wi, Wu, Wo, bf, bi, bu, bo);
    bias_fold_k<<<128, 256>>>(bc);

    // Wfold[256:512] = Wc @ Wall[256:512]
    gemm_tc<false, false, false><<<dim3(1024 / 128, 256 / 128, 1), 256>>>(
        Wc, nullptr, Wall + 256 * 1024, Wfold + 256 * 1024, nullptr,
        256, 1024, 256, 256, 1024, 1024, 0, 0, 0);

    // Q = X @ rot ; K = X @ ent
    gemm_tc<false, false, false><<<dim3(E_ / 128, TB_ / 128, 1), 256>>>(
        inputs, nullptr, rot, Q, nullptr, TB_, E_, E_, E_, E_, E_, 0, 0, 0);
    gemm_tc<false, false, false><<<dim3(E_ / 128, TB_ / 128, 1), 256>>>(
        inputs, nullptr, ent, K, nullptr, TB_, E_, E_, E_, E_, E_, 0, 0, 0);

    // scores_b = Q_b @ K_b^T
    gemm_tc<true, false, false><<<dim3(T_ / 128, T_ / 128, B_), 256>>>(
        Q, nullptr, K, S, nullptr, T_, T_, E_, B_ * E_, B_ * E_, T_,
        (long)E_, (long)E_, (long)T_ * T_);

    softmax_k<<<B_ * T_, 128>>>(S);

    // context_b = S_b @ X_b
    gemm_tc<false, false, false><<<dim3(E_ / 128, T_ / 128, B_), 256>>>(
        S, nullptr, inputs, CTX, nullptr, T_, E_, T_, T_, B_ * E_, B_ * E_,
        (long)T_ * T_, (long)E_, (long)E_);

    // PRE = [X | CTX] @ Wfold + bfold
    gemm_tc<false, true, true><<<dim3(1024 / 128, TB_ / 128, 1), 256>>>(
        inputs, CTX, Wfold, PRE, bfold, TB_, 1024, 512, E_, 1024, 1024, 0, 0, 0);

    recur10_k<<<64, 256, RSMEM>>>(PRE, out);
    (void)in_sizes; (void)n_in; (void)out_size;
}

// round 16
// speedup vs baseline: 1.1979x; 1.0066x over previous
#include <cuda_runtime.h>
#include <math.h>

#define T_  512
#define B_  64
#define E_  256
#define H_  256
#define TB_ (T_ * B_)          // 32768
#define CLU 8                  // CTAs per cluster
#define BGR 8                  // batch elements per cluster

// ---------------- static device scratch ----------------
__device__ float g_Q  [TB_ * E_];
__device__ float g_K  [TB_ * E_];
__device__ float g_S  [B_ * T_ * T_];
__device__ float g_CTX[TB_ * E_];
__device__ float g_PRE[(long)TB_ * 4 * H_];
__device__ float g_Wall [512 * 1024];      // packed [Wf|Wi|Wu|Wo] as (512, 1024)
__device__ float g_Wfold[512 * 1024];      // rows 0..255 = Wx; rows 256..511 = Wc@Wh
__device__ float g_ball [1024];
__device__ float g_bfold[1024];            // bc@Wh + b
// recurrent W for MMA (R13 layout): bf16 split pairs along k, [rank][c(128)][kp(140 pad)]
__device__ unsigned g_WAh[CLU * 128 * 140];
__device__ unsigned g_WAl[CLU * 128 * 140];

// ---------------- bf16 2-split helpers ----------------
__device__ __forceinline__ void split_bf2(float e, float o, unsigned& hi, unsigned& lo)
{
    unsigned h;
    asm("cvt.rn.bf16x2.f32 %0, %1, %2;" : "=r"(h) : "f"(o), "f"(e));
    float eh = __uint_as_float(h << 16);
    float oh = __uint_as_float(h & 0xffff0000u);
    unsigned l;
    asm("cvt.rn.bf16x2.f32 %0, %1, %2;" : "=r"(l) : "f"(o - oh), "f"(e - eh));
    hi = h; lo = l;
}

#define MMA_BF16(c, a, b)                                                          \
    asm volatile("mma.sync.aligned.m16n8k16.row.col.f32.bf16.bf16.f32 "            \
                 "{%0,%1,%2,%3},{%4,%5,%6,%7},{%8,%9},{%0,%1,%2,%3};"              \
                 : "+f"(c[0]), "+f"(c[1]), "+f"(c[2]), "+f"(c[3])                  \
                 : "r"(a[0]), "r"(a[1]), "r"(a[2]), "r"(a[3]),                     \
                   "r"(b[0]), "r"(b[1]))

// ---------------- tensor-core bf16 GEMM, 128x128x16 tile, 3x split, occ 2 ----
// (exact proven R8/R12 version)
template<bool NT, bool BIAS, bool CONCAT>
__global__ void __launch_bounds__(256, 2) gemm_tc(
    const float* __restrict__ A, const float* __restrict__ A2,
    const float* __restrict__ B, float* __restrict__ C,
    const float* __restrict__ bias,
    int M, int N, int K, int lda, int ldb, int ldc,
    long sA, long sB, long sC)
{
    A += (long)blockIdx.z * sA;
    B += (long)blockIdx.z * sB;
    C += (long)blockIdx.z * sC;

    __shared__ unsigned As_hi[8][136], As_lo[8][136];
    __shared__ unsigned Bs_hi[8][136], Bs_lo[8][136];

    const int tid  = threadIdx.x;
    const int lane = tid & 31;
    const int warp = tid >> 5;
    const int m0 = blockIdx.y * 128;
    const int n0 = blockIdx.x * 128;
    const int wm = (warp >> 2) * 64;
    const int wn = (warp & 3) * 32;
    const int gq = lane >> 2;
    const int tg = lane & 3;

    const int ar = tid & 127;
    const int aq = (tid >> 7) * 4;
    const int bkr = tid >> 5;
    const int bn  = (tid & 31) * 4;
    const int bn_t = tid & 127;
    const int bq   = (tid >> 7) * 4;

    float acc[4][4][4];
    #pragma unroll
    for (int i = 0; i < 4; ++i)
        #pragma unroll
        for (int j = 0; j < 4; ++j)
            #pragma unroll
            for (int q = 0; q < 4; ++q) acc[i][j][q] = 0.f;

    float4 va0, va1, vb0, vb1;
    auto load_tile = [&](int k0) {
        const float* Ab = A;
        int kc = k0;
        if (CONCAT) { if (k0 >= 256) { Ab = A2; kc = k0 - 256; } }
        va0 = *(const float4*)(Ab + (long)(m0 + ar) * lda + kc + aq);
        va1 = *(const float4*)(Ab + (long)(m0 + ar) * lda + kc + aq + 8);
        if (NT) {
            vb0 = *(const float4*)(B + (long)(n0 + bn_t) * ldb + k0 + bq);
            vb1 = *(const float4*)(B + (long)(n0 + bn_t) * ldb + k0 + bq + 8);
        } else {
            vb0 = *(const float4*)(B + (long)(k0 + 2 * bkr) * ldb + n0 + bn);
            vb1 = *(const float4*)(B + (long)(k0 + 2 * bkr + 1) * ldb + n0 + bn);
        }
    };

    load_tile(0);

    for (int k0 = 0; k0 < K; k0 += 16) {
        __syncthreads();
        {
            int kp = aq >> 1;
            split_bf2(va0.x, va0.y, As_hi[kp    ][ar], As_lo[kp    ][ar]);
            split_bf2(va0.z, va0.w, As_hi[kp + 1][ar], As_lo[kp + 1][ar]);
            split_bf2(va1.x, va1.y, As_hi[kp + 4][ar], As_lo[kp + 4][ar]);
            split_bf2(va1.z, va1.w, As_hi[kp + 5][ar], As_lo[kp + 5][ar]);
            if (NT) {
                int bp = bq >> 1;
                split_bf2(vb0.x, vb0.y, Bs_hi[bp    ][bn_t], Bs_lo[bp    ][bn_t]);
                split_bf2(vb0.z, vb0.w, Bs_hi[bp + 1][bn_t], Bs_lo[bp + 1][bn_t]);
                split_bf2(vb1.x, vb1.y, Bs_hi[bp + 4][bn_t], Bs_lo[bp + 4][bn_t]);
                split_bf2(vb1.z, vb1.w, Bs_hi[bp + 5][bn_t], Bs_lo[bp + 5][bn_t]);
            } else {
                uint4 h4, l4;
                split_bf2(vb0.x, vb1.x, h4.x, l4.x);
                split_bf2(vb0.y, vb1.y, h4.y, l4.y);
                split_bf2(vb0.z, vb1.z, h4.z, l4.z);
                split_bf2(vb0.w, vb1.w, h4.w, l4.w);
                *(uint4*)&Bs_hi[bkr][bn] = h4;
                *(uint4*)&Bs_lo[bkr][bn] = l4;
            }
        }
        __syncthreads();

        int kn = (k0 + 16 < K) ? k0 + 16 : k0;
        load_tile(kn);

        unsigned ah[4][4], al[4][4], bh[4][2], bl[4][2];
        #pragma unroll
        for (int i = 0; i < 4; ++i) {
            int r = wm + i * 16 + gq;
            ah[i][0] = As_hi[tg    ][r];
            ah[i][1] = As_hi[tg    ][r + 8];
            ah[i][2] = As_hi[tg + 4][r];
            ah[i][3] = As_hi[tg + 4][r + 8];
            al[i][0] = As_lo[tg    ][r];
            al[i][1] = As_lo[tg    ][r + 8];
            al[i][2] = As_lo[tg + 4][r];
            al[i][3] = As_lo[tg + 4][r + 8];
        }
        #pragma unroll
        for (int j = 0; j < 4; ++j) {
            int n = wn + j * 8 + gq;
            bh[j][0] = Bs_hi[tg    ][n];
            bh[j][1] = Bs_hi[tg + 4][n];
            bl[j][0] = Bs_lo[tg    ][n];
            bl[j][1] = Bs_lo[tg + 4][n];
        }
        #pragma unroll
        for (int i = 0; i < 4; ++i)
            #pragma unroll
            for (int j = 0; j < 4; ++j) {
                MMA_BF16(acc[i][j], ah[i], bh[j]);
                MMA_BF16(acc[i][j], al[i], bh[j]);
                MMA_BF16(acc[i][j], ah[i], bl[j]);
            }
    }

    #pragma unroll
    for (int i = 0; i < 4; ++i)
        #pragma unroll
        for (int j = 0; j < 4; ++j) {
            int m = m0 + wm + i * 16 + gq;
            int n = n0 + wn + j * 8 + 2 * tg;
            float2 v0 = make_float2(acc[i][j][0], acc[i][j][1]);
            float2 v1 = make_float2(acc[i][j][2], acc[i][j][3]);
            if (BIAS) {
                float b0 = bias[n], b1 = bias[n + 1];
                v0.x += b0; v0.y += b1;
                v1.x += b0; v1.y += b1;
            }
            *(float2*)(C + (long)m * ldc + n)       = v0;
            *(float2*)(C + (long)(m + 8) * ldc + n) = v1;
        }
}

// ---------------- softmax over rows of length 512 ----------
__global__ void __launch_bounds__(128) softmax_k(float* __restrict__ S)
{
    float* p = S + (long)blockIdx.x * 512;
    int tid = threadIdx.x;
    float v[4];
    float m = -1e30f;
    #pragma unroll
    for (int i = 0; i < 4; ++i) { v[i] = p[tid + 128 * i] * 0.0625f; m = fmaxf(m, v[i]); }
    __shared__ float red[128];
    red[tid] = m; __syncthreads();
    for (int s = 64; s > 0; s >>= 1) { if (tid < s) red[tid] = fmaxf(red[tid], red[tid + s]); __syncthreads(); }
    m = red[0]; __syncthreads();
    float sum = 0.f;
    #pragma unroll
    for (int i = 0; i < 4; ++i) { v[i] = __expf(v[i] - m); sum += v[i]; }
    red[tid] = sum; __syncthreads();
    for (int s = 64; s > 0; s >>= 1) { if (tid < s) red[tid] += red[tid + s]; __syncthreads(); }
    float inv = 1.f / red[0];
    #pragma unroll
    for (int i = 0; i < 4; ++i) p[tid + 128 * i] = v[i] * inv;
}

// ---------------- pack weights (R13 layout) ----------------
__global__ void pack_init_k(const float* __restrict__ Wf, const float* __restrict__ Wi,
                            const float* __restrict__ Wu, const float* __restrict__ Wo,
                            const float* __restrict__ bf, const float* __restrict__ bi,
                            const float* __restrict__ bu, const float* __restrict__ bo)
{
    int idx = blockIdx.x * blockDim.x + threadIdx.x;
    int nt = gridDim.x * blockDim.x;
    for (int i = idx; i < CLU * 128 * 128; i += nt) {
        int r   = i >> 14;
        int c   = (i >> 7) & 127;
        int kp  = i & 127;
        int jl  = ((c >> 4) << 2) + (c & 3);
        int g   = (c >> 2) & 3;
        int j   = r * 32 + jl;
        const float* W = (g == 0) ? Wf : (g == 1) ? Wi : (g == 2) ? Wu : Wo;
        float w0 = W[(E_ + 2 * kp) * H_ + j];
        float w1 = W[(E_ + 2 * kp + 1) * H_ + j];
        unsigned hi, lo;
        split_bf2(w0, w1, hi, lo);
        long o = (long)r * (128 * 140) + c * 140 + kp;
        g_WAh[o] = hi;
        g_WAl[o] = lo;
    }
    for (int i = idx; i < 512 * 1024; i += nt) {
        int k = i >> 10;
        int col = i & 1023;
        int g = col >> 8, j = col & 255;
        const float* W = (g == 0) ? Wf : (g == 1) ? Wi : (g == 2) ? Wu : Wo;
        float v = W[k * 256 + j];
        g_Wall[i] = v;
        if (i < 256 * 1024) g_Wfold[i] = v;
    }
    for (int i = idx; i < 1024; i += nt) {
        int g = i >> 8;
        const float* b = (g == 0) ? bf : (g == 1) ? bi : (g == 2) ? bu : bo;
        g_ball[i] = b[i & 255];
    }
}

// bfold[col] = ball[col] + sum_h bc[h] * Wall[256+h][col]
__global__ void __launch_bounds__(256) bias_fold_k(const float* __restrict__ bc)
{
    int col  = blockIdx.x * 8 + (threadIdx.x >> 5);
    int lane = threadIdx.x & 31;
    float s = 0.f;
    #pragma unroll
    for (int h = lane; h < 256; h += 32)
        s += bc[h] * g_Wall[(256 + h) * 1024 + col];
    #pragma unroll
    for (int o = 16; o > 0; o >>= 1)
        s += __shfl_xor_sync(0xffffffffu, s, o);
    if (lane == 0) g_bfold[col] = g_ball[col] + s;
}

__device__ __forceinline__ float sigf(float x)  { return 1.f / (1.f + __expf(-x)); }
__device__ __forceinline__ float tanhf_(float x){ return 2.f / (1.f + __expf(-2.f * x)) - 1.f; }

#define CARRIVE() asm volatile("barrier.cluster.arrive.aligned;" ::: "memory")
#define CWAIT()   asm volatile("barrier.cluster.wait.aligned;"   ::: "memory")

// ------------- cluster LSTM recurrence: reg-resident W, 3 indep MMA chains ---
// Same as proven R15 recur10_k, but the three split terms accumulate into
// SEPARATE accumulator sets (independent 16-deep HMMA chains instead of one
// 48-deep chain); summed once before the gate exchange.
__global__ void __launch_bounds__(256, 1) __cluster_dims__(CLU, 1, 1)
recur11_k(const float* __restrict__ PRE, float* __restrict__ out)
{
    extern __shared__ float hbuf[];          // [2 buf][256 k][12]

    const int tid  = threadIdx.x;
    const int lane = tid & 31;
    const int warp = tid >> 5;
    const int gq = lane >> 2;
    const int tg = lane & 3;
    unsigned rank;
    asm("mov.u32 %0, %%cluster_ctarank;" : "=r"(rank));
    const int bg0 = (blockIdx.x >> 3) * BGR;

    for (int m = tid; m < 6144; m += 256) hbuf[m] = 0.f;

    // load this lane's A fragments into registers, once
    unsigned avh[16][4], avl[16][4];
    {
        const unsigned* wh0 = g_WAh + (long)rank * 17920 + (warp * 16 + gq) * 140;
        const unsigned* wh1 = g_WAh + (long)rank * 17920 + (warp * 16 + gq + 8) * 140;
        const unsigned* wl0 = g_WAl + (long)rank * 17920 + (warp * 16 + gq) * 140;
        const unsigned* wl1 = g_WAl + (long)rank * 17920 + (warp * 16 + gq + 8) * 140;
        #pragma unroll
        for (int ks = 0; ks < 16; ++ks) {
            const int kp = ks * 8 + tg;
            avh[ks][0] = wh0[kp];     avh[ks][1] = wh1[kp];
            avh[ks][2] = wh0[kp + 4]; avh[ks][3] = wh1[kp + 4];
            avl[ks][0] = wl0[kp];     avl[ks][1] = wl1[kp];
            avl[ks][2] = wl0[kp + 4]; avl[ks][3] = wl1[kp + 4];
        }
    }

    // cell identity for this lane
    const int jl    = warp * 4 + (gq & 3);
    const int jg    = rank * 32 + jl;
    const int b     = 2 * tg + (gq >> 2);
    const int bglob = bg0 + b;

    float creg = 0.f, hreg = 0.f;
    float p0, p1, p2, p3;
    {
        const float* pp = PRE + (long)bglob * 1024 + jg;
        p0 = pp[0]; p1 = pp[256]; p2 = pp[512]; p3 = pp[768];
    }

    const unsigned hb_u32 = (unsigned)__cvta_generic_to_shared(hbuf);

    __syncthreads();
    CARRIVE(); CWAIT();

    for (int t = 0; t < T_; ++t) {
        const int buf = t & 1;
        const float* hp = hbuf + buf * 3072;

        float ahh[4] = {0.f, 0.f, 0.f, 0.f};
        float alh[4] = {0.f, 0.f, 0.f, 0.f};
        float ahl[4] = {0.f, 0.f, 0.f, 0.f};
        #pragma unroll
        for (int ks = 0; ks < 16; ++ks) {
            const int k0 = ks * 16 + tg * 2;
            float h00 = hp[(k0    ) * 12 + gq];
            float h01 = hp[(k0 + 1) * 12 + gq];
            float h10 = hp[(k0 + 8) * 12 + gq];
            float h11 = hp[(k0 + 9) * 12 + gq];
            unsigned b0h, b0l, b1h, b1l;
            split_bf2(h00, h01, b0h, b0l);
            split_bf2(h10, h11, b1h, b1l);
            unsigned bvh[2] = {b0h, b1h};
            unsigned bvl[2] = {b0l, b1l};
            MMA_BF16(ahh, avh[ks], bvh);
            MMA_BF16(alh, avl[ks], bvh);
            MMA_BF16(ahl, avh[ks], bvl);
        }
        float acc[4];
        #pragma unroll
        for (int q = 0; q < 4; ++q) acc[q] = ahh[q] + alh[q] + ahl[q];

        // pair gate owners: lane^16 flips gq bit2
        float r0 = __shfl_xor_sync(0xffffffffu, acc[0], 16);
        float r1 = __shfl_xor_sync(0xffffffffu, acc[1], 16);
        float r2 = __shfl_xor_sync(0xffffffffu, acc[2], 16);
        float r3 = __shfl_xor_sync(0xffffffffu, acc[3], 16);
        float s0, s1, s2, s3;
        if (gq < 4) { s0 = acc[0]; s1 = r0;     s2 = acc[2]; s3 = r2;     }
        else        { s0 = r1;     s1 = acc[1]; s2 = r3;     s3 = acc[3]; }

        float fg = sigf  (s0 + p0);
        float ig = sigf  (s1 + p1);
        float ug = tanhf_(s2 + p2);
        float og = sigf  (s3 + p3);
        creg = fg * creg + ig * ug;
        hreg = og * tanhf_(creg);
        out[((long)t * B_ + bglob) * H_ + jg] = hreg;

        // publish h to all cluster CTAs' hbuf[buf^1]
        unsigned laddr = hb_u32 + ((((buf ^ 1) * 256 + jg) * 12 + b) << 2);
        #pragma unroll
        for (int rr = 0; rr < CLU; ++rr) {
            unsigned ra;
            asm volatile("mapa.shared::cluster.u32 %0, %1, %2;"
                         : "=r"(ra) : "r"(laddr), "r"(rr));
            asm volatile("st.shared::cluster.f32 [%0], %1;"
                         :: "r"(ra), "f"(hreg) : "memory");
        }

        // prefetch next step's PRE
        int tn = (t < T_ - 1) ? t + 1 : t;
        const float* pq = PRE + ((long)tn * B_ + bglob) * 1024 + jg;
        p0 = pq[0]; p1 = pq[256]; p2 = pq[512]; p3 = pq[768];

        CARRIVE();
        CWAIT();
    }

    out[(long)TB_ * H_ + bglob * H_ + jg] = hreg;                 // hx
    out[(long)TB_ * H_ + (long)B_ * H_ + bglob * H_ + jg] = creg; // cx
}

// ---------------- launch ----------------
extern "C" void kernel_launch(void* const* d_in, const int* in_sizes, int n_in,
                              void* d_out, int out_size)
{
    const float* inputs = (const float*)d_in[0];
    const float* rot    = (const float*)d_in[1];
    const float* ent    = (const float*)d_in[2];
    const float* Wf = (const float*)d_in[3];  const float* bf = (const float*)d_in[4];
    const float* Wi = (const float*)d_in[5];  const float* bi = (const float*)d_in[6];
    const float* Wu = (const float*)d_in[7];  const float* bu = (const float*)d_in[8];
    const float* Wo = (const float*)d_in[9];  const float* bo = (const float*)d_in[10];
    const float* Wc = (const float*)d_in[11]; const float* bc = (const float*)d_in[12];
    float* out = (float*)d_out;

    float *Q, *K, *S, *CTX, *PRE, *Wall, *Wfold, *bfold;
    cudaGetSymbolAddress((void**)&Q,     g_Q);
    cudaGetSymbolAddress((void**)&K,     g_K);
    cudaGetSymbolAddress((void**)&S,     g_S);
    cudaGetSymbolAddress((void**)&CTX,   g_CTX);
    cudaGetSymbolAddress((void**)&PRE,   g_PRE);
    cudaGetSymbolAddress((void**)&Wall,  g_Wall);
    cudaGetSymbolAddress((void**)&Wfold, g_Wfold);
    cudaGetSymbolAddress((void**)&bfold, g_bfold);

    const int RSMEM = 6144 * 4;   // 24576 B (hbuf only)
    cudaFuncSetAttribute(recur11_k, cudaFuncAttributeMaxDynamicSharedMemorySize, RSMEM);

    pack_init_k<<<256, 256>>>(Wf, Wi, Wu, Wo, bf, bi, bu, bo);
    bias_fold_k<<<128, 256>>>(bc);

    // Wfold[256:512] = Wc @ Wall[256:512]
    gemm_tc<false, false, false><<<dim3(1024 / 128, 256 / 128, 1), 256>>>(
        Wc, nullptr, Wall + 256 * 1024, Wfold + 256 * 1024, nullptr,
        256, 1024, 256, 256, 1024, 1024, 0, 0, 0);

    // Q = X @ rot ; K = X @ ent
    gemm_tc<false, false, false><<<dim3(E_ / 128, TB_ / 128, 1), 256>>>(
        inputs, nullptr, rot, Q, nullptr, TB_, E_, E_, E_, E_, E_, 0, 0, 0);
    gemm_tc<false, false, false><<<dim3(E_ / 128, TB_ / 128, 1), 256>>>(
        inputs, nullptr, ent, K, nullptr, TB_, E_, E_, E_, E_, E_, 0, 0, 0);

    // scores_b = Q_b @ K_b^T
    gemm_tc<true, false, false><<<dim3(T_ / 128, T_ / 128, B_), 256>>>(
        Q, nullptr, K, S, nullptr, T_, T_, E_, B_ * E_, B_ * E_, T_,
        (long)E_, (long)E_, (long)T_ * T_);

    softmax_k<<<B_ * T_, 128>>>(S);

    // context_b = S_b @ X_b
    gemm_tc<false, false, false><<<dim3(E_ / 128, T_ / 128, B_), 256>>>(
        S, nullptr, inputs, CTX, nullptr, T_, E_, T_, T_, B_ * E_, B_ * E_,
        (long)T_ * T_, (long)E_, (long)E_);

    // PRE = [X | CTX] @ Wfold + bfold
    gemm_tc<false, true, true><<<dim3(1024 / 128, TB_ / 128, 1), 256>>>(
        inputs, CTX, Wfold, PRE, bfold, TB_, 1024, 512, E_, 1024, 1024, 0, 0, 0);

    recur11_k<<<64, 256, RSMEM>>>(PRE, out);
    (void)in_sizes; (void)n_in; (void)out_size;
}

// round 17
// speedup vs baseline: 1.2999x; 1.0852x over previous
#include <cuda_runtime.h>
#include <math.h>

#define T_  512
#define B_  64
#define E_  256
#define H_  256
#define TB_ (T_ * B_)          // 32768
#define CLU 8                  // CTAs per cluster
#define BGR 8                  // batch elements per cluster

// ---------------- static device scratch ----------------
__device__ float g_Q  [TB_ * E_];
__device__ float g_K  [TB_ * E_];
__device__ float g_S  [B_ * T_ * T_];
__device__ float g_CTX[TB_ * E_];
__device__ float g_PRE[(long)TB_ * 4 * H_];
__device__ float g_Wall [512 * 1024];      // packed [Wf|Wi|Wu|Wo] as (512, 1024)
__device__ float g_Wfold[512 * 1024];      // rows 0..255 = Wx; rows 256..511 = Wc@Wh
__device__ float g_ball [1024];
__device__ float g_bfold[1024];            // bc@Wh + b
// recurrent W for MMA (R13 layout): bf16 split pairs along k, [rank][c(128)][kp(140 pad)]
__device__ unsigned g_WAh[CLU * 128 * 140];
__device__ unsigned g_WAl[CLU * 128 * 140];

// ---------------- bf16 2-split helpers ----------------
__device__ __forceinline__ void split_bf2(float e, float o, unsigned& hi, unsigned& lo)
{
    unsigned h;
    asm("cvt.rn.bf16x2.f32 %0, %1, %2;" : "=r"(h) : "f"(o), "f"(e));
    float eh = __uint_as_float(h << 16);
    float oh = __uint_as_float(h & 0xffff0000u);
    unsigned l;
    asm("cvt.rn.bf16x2.f32 %0, %1, %2;" : "=r"(l) : "f"(o - oh), "f"(e - eh));
    hi = h; lo = l;
}

#define MMA_BF16(c, a, b)                                                          \
    asm volatile("mma.sync.aligned.m16n8k16.row.col.f32.bf16.bf16.f32 "            \
                 "{%0,%1,%2,%3},{%4,%5,%6,%7},{%8,%9},{%0,%1,%2,%3};"              \
                 : "+f"(c[0]), "+f"(c[1]), "+f"(c[2]), "+f"(c[3])                  \
                 : "r"(a[0]), "r"(a[1]), "r"(a[2]), "r"(a[3]),                     \
                   "r"(b[0]), "r"(b[1]))

// ---------------- tensor-core bf16 GEMM, 128x128x16 tile, 3x split, occ 2 ----
// (exact proven R8/R12 version)
template<bool NT, bool BIAS, bool CONCAT>
__global__ void __launch_bounds__(256, 2) gemm_tc(
    const float* __restrict__ A, const float* __restrict__ A2,
    const float* __restrict__ B, float* __restrict__ C,
    const float* __restrict__ bias,
    int M, int N, int K, int lda, int ldb, int ldc,
    long sA, long sB, long sC)
{
    A += (long)blockIdx.z * sA;
    B += (long)blockIdx.z * sB;
    C += (long)blockIdx.z * sC;

    __shared__ unsigned As_hi[8][136], As_lo[8][136];
    __shared__ unsigned Bs_hi[8][136], Bs_lo[8][136];

    const int tid  = threadIdx.x;
    const int lane = tid & 31;
    const int warp = tid >> 5;
    const int m0 = blockIdx.y * 128;
    const int n0 = blockIdx.x * 128;
    const int wm = (warp >> 2) * 64;
    const int wn = (warp & 3) * 32;
    const int gq = lane >> 2;
    const int tg = lane & 3;

    const int ar = tid & 127;
    const int aq = (tid >> 7) * 4;
    const int bkr = tid >> 5;
    const int bn  = (tid & 31) * 4;
    const int bn_t = tid & 127;
    const int bq   = (tid >> 7) * 4;

    float acc[4][4][4];
    #pragma unroll
    for (int i = 0; i < 4; ++i)
        #pragma unroll
        for (int j = 0; j < 4; ++j)
            #pragma unroll
            for (int q = 0; q < 4; ++q) acc[i][j][q] = 0.f;

    float4 va0, va1, vb0, vb1;
    auto load_tile = [&](int k0) {
        const float* Ab = A;
        int kc = k0;
        if (CONCAT) { if (k0 >= 256) { Ab = A2; kc = k0 - 256; } }
        va0 = *(const float4*)(Ab + (long)(m0 + ar) * lda + kc + aq);
        va1 = *(const float4*)(Ab + (long)(m0 + ar) * lda + kc + aq + 8);
        if (NT) {
            vb0 = *(const float4*)(B + (long)(n0 + bn_t) * ldb + k0 + bq);
            vb1 = *(const float4*)(B + (long)(n0 + bn_t) * ldb + k0 + bq + 8);
        } else {
            vb0 = *(const float4*)(B + (long)(k0 + 2 * bkr) * ldb + n0 + bn);
            vb1 = *(const float4*)(B + (long)(k0 + 2 * bkr + 1) * ldb + n0 + bn);
        }
    };

    load_tile(0);

    for (int k0 = 0; k0 < K; k0 += 16) {
        __syncthreads();
        {
            int kp = aq >> 1;
            split_bf2(va0.x, va0.y, As_hi[kp    ][ar], As_lo[kp    ][ar]);
            split_bf2(va0.z, va0.w, As_hi[kp + 1][ar], As_lo[kp + 1][ar]);
            split_bf2(va1.x, va1.y, As_hi[kp + 4][ar], As_lo[kp + 4][ar]);
            split_bf2(va1.z, va1.w, As_hi[kp + 5][ar], As_lo[kp + 5][ar]);
            if (NT) {
                int bp = bq >> 1;
                split_bf2(vb0.x, vb0.y, Bs_hi[bp    ][bn_t], Bs_lo[bp    ][bn_t]);
                split_bf2(vb0.z, vb0.w, Bs_hi[bp + 1][bn_t], Bs_lo[bp + 1][bn_t]);
                split_bf2(vb1.x, vb1.y, Bs_hi[bp + 4][bn_t], Bs_lo[bp + 4][bn_t]);
                split_bf2(vb1.z, vb1.w, Bs_hi[bp + 5][bn_t], Bs_lo[bp + 5][bn_t]);
            } else {
                uint4 h4, l4;
                split_bf2(vb0.x, vb1.x, h4.x, l4.x);
                split_bf2(vb0.y, vb1.y, h4.y, l4.y);
                split_bf2(vb0.z, vb1.z, h4.z, l4.z);
                split_bf2(vb0.w, vb1.w, h4.w, l4.w);
                *(uint4*)&Bs_hi[bkr][bn] = h4;
                *(uint4*)&Bs_lo[bkr][bn] = l4;
            }
        }
        __syncthreads();

        int kn = (k0 + 16 < K) ? k0 + 16 : k0;
        load_tile(kn);

        unsigned ah[4][4], al[4][4], bh[4][2], bl[4][2];
        #pragma unroll
        for (int i = 0; i < 4; ++i) {
            int r = wm + i * 16 + gq;
            ah[i][0] = As_hi[tg    ][r];
            ah[i][1] = As_hi[tg    ][r + 8];
            ah[i][2] = As_hi[tg + 4][r];
            ah[i][3] = As_hi[tg + 4][r + 8];
            al[i][0] = As_lo[tg    ][r];
            al[i][1] = As_lo[tg    ][r + 8];
            al[i][2] = As_lo[tg + 4][r];
            al[i][3] = As_lo[tg + 4][r + 8];
        }
        #pragma unroll
        for (int j = 0; j < 4; ++j) {
            int n = wn + j * 8 + gq;
            bh[j][0] = Bs_hi[tg    ][n];
            bh[j][1] = Bs_hi[tg + 4][n];
            bl[j][0] = Bs_lo[tg    ][n];
            bl[j][1] = Bs_lo[tg + 4][n];
        }
        #pragma unroll
        for (int i = 0; i < 4; ++i)
            #pragma unroll
            for (int j = 0; j < 4; ++j) {
                MMA_BF16(acc[i][j], ah[i], bh[j]);
                MMA_BF16(acc[i][j], al[i], bh[j]);
                MMA_BF16(acc[i][j], ah[i], bl[j]);
            }
    }

    #pragma unroll
    for (int i = 0; i < 4; ++i)
        #pragma unroll
        for (int j = 0; j < 4; ++j) {
            int m = m0 + wm + i * 16 + gq;
            int n = n0 + wn + j * 8 + 2 * tg;
            float2 v0 = make_float2(acc[i][j][0], acc[i][j][1]);
            float2 v1 = make_float2(acc[i][j][2], acc[i][j][3]);
            if (BIAS) {
                float b0 = bias[n], b1 = bias[n + 1];
                v0.x += b0; v0.y += b1;
                v1.x += b0; v1.y += b1;
            }
            *(float2*)(C + (long)m * ldc + n)       = v0;
            *(float2*)(C + (long)(m + 8) * ldc + n) = v1;
        }
}

// ---------------- softmax over rows of length 512 ----------
__global__ void __launch_bounds__(128) softmax_k(float* __restrict__ S)
{
    float* p = S + (long)blockIdx.x * 512;
    int tid = threadIdx.x;
    float v[4];
    float m = -1e30f;
    #pragma unroll
    for (int i = 0; i < 4; ++i) { v[i] = p[tid + 128 * i] * 0.0625f; m = fmaxf(m, v[i]); }
    __shared__ float red[128];
    red[tid] = m; __syncthreads();
    for (int s = 64; s > 0; s >>= 1) { if (tid < s) red[tid] = fmaxf(red[tid], red[tid + s]); __syncthreads(); }
    m = red[0]; __syncthreads();
    float sum = 0.f;
    #pragma unroll
    for (int i = 0; i < 4; ++i) { v[i] = __expf(v[i] - m); sum += v[i]; }
    red[tid] = sum; __syncthreads();
    for (int s = 64; s > 0; s >>= 1) { if (tid < s) red[tid] += red[tid + s]; __syncthreads(); }
    float inv = 1.f / red[0];
    #pragma unroll
    for (int i = 0; i < 4; ++i) p[tid + 128 * i] = v[i] * inv;
}

// ---------------- pack weights (R13 layout) ----------------
__global__ void pack_init_k(const float* __restrict__ Wf, const float* __restrict__ Wi,
                            const float* __restrict__ Wu, const float* __restrict__ Wo,
                            const float* __restrict__ bf, const float* __restrict__ bi,
                            const float* __restrict__ bu, const float* __restrict__ bo)
{
    int idx = blockIdx.x * blockDim.x + threadIdx.x;
    int nt = gridDim.x * blockDim.x;
    for (int i = idx; i < CLU * 128 * 128; i += nt) {
        int r   = i >> 14;
        int c   = (i >> 7) & 127;
        int kp  = i & 127;
        int jl  = ((c >> 4) << 2) + (c & 3);
        int g   = (c >> 2) & 3;
        int j   = r * 32 + jl;
        const float* W = (g == 0) ? Wf : (g == 1) ? Wi : (g == 2) ? Wu : Wo;
        float w0 = W[(E_ + 2 * kp) * H_ + j];
        float w1 = W[(E_ + 2 * kp + 1) * H_ + j];
        unsigned hi, lo;
        split_bf2(w0, w1, hi, lo);
        long o = (long)r * (128 * 140) + c * 140 + kp;
        g_WAh[o] = hi;
        g_WAl[o] = lo;
    }
    for (int i = idx; i < 512 * 1024; i += nt) {
        int k = i >> 10;
        int col = i & 1023;
        int g = col >> 8, j = col & 255;
        const float* W = (g == 0) ? Wf : (g == 1) ? Wi : (g == 2) ? Wu : Wo;
        float v = W[k * 256 + j];
        g_Wall[i] = v;
        if (i < 256 * 1024) g_Wfold[i] = v;
    }
    for (int i = idx; i < 1024; i += nt) {
        int g = i >> 8;
        const float* b = (g == 0) ? bf : (g == 1) ? bi : (g == 2) ? bu : bo;
        g_ball[i] = b[i & 255];
    }
}

// bfold[col] = ball[col] + sum_h bc[h] * Wall[256+h][col]
__global__ void __launch_bounds__(256) bias_fold_k(const float* __restrict__ bc)
{
    int col  = blockIdx.x * 8 + (threadIdx.x >> 5);
    int lane = threadIdx.x & 31;
    float s = 0.f;
    #pragma unroll
    for (int h = lane; h < 256; h += 32)
        s += bc[h] * g_Wall[(256 + h) * 1024 + col];
    #pragma unroll
    for (int o = 16; o > 0; o >>= 1)
        s += __shfl_xor_sync(0xffffffffu, s, o);
    if (lane == 0) g_bfold[col] = g_ball[col] + s;
}

__device__ __forceinline__ float sigf(float x)  { return 1.f / (1.f + __expf(-x)); }
__device__ __forceinline__ float tanhf_(float x){ return 2.f / (1.f + __expf(-2.f * x)) - 1.f; }

#define CARRIVE() asm volatile("barrier.cluster.arrive.aligned;" ::: "memory")
#define CWAIT()   asm volatile("barrier.cluster.wait.aligned;"   ::: "memory")

// cluster-scope mbarrier parity wait (acquire)
__device__ __forceinline__ void mbar_wait_clu(unsigned mbar, unsigned parity)
{
    unsigned done;
    asm volatile(
        "{\n\t.reg .pred P;\n\t"
        "mbarrier.try_wait.parity.acquire.cluster.shared::cta.b64 P, [%1], %2;\n\t"
        "selp.b32 %0, 1, 0, P;\n\t}"
        : "=r"(done) : "r"(mbar), "r"(parity) : "memory");
    while (!done) {
        asm volatile(
            "{\n\t.reg .pred P;\n\t"
            "mbarrier.try_wait.parity.acquire.cluster.shared::cta.b64 P, [%1], %2, 0x989680;\n\t"
            "selp.b32 %0, 1, 0, P;\n\t}"
            : "=r"(done) : "r"(mbar), "r"(parity) : "memory");
    }
}

// ------ cluster LSTM recurrence: st.async + mbarrier tx protocol -------------
// No barrier.cluster / syncthreads in the time loop. Each CTA has 2 mbarriers
// (one per h buffer). Publishes use st.async (remote store + complete_tx on the
// target's mbarrier). expect_tx = 2048 values * 4B = 8192B per phase.
__global__ void __launch_bounds__(256, 1) __cluster_dims__(CLU, 1, 1)
recur12_k(const float* __restrict__ PRE, float* __restrict__ out)
{
    extern __shared__ float hbuf[];          // [2 buf][256 k][12] + 2 mbarriers

    const int tid  = threadIdx.x;
    const int lane = tid & 31;
    const int warp = tid >> 5;
    const int gq = lane >> 2;
    const int tg = lane & 3;
    unsigned rank;
    asm("mov.u32 %0, %%cluster_ctarank;" : "=r"(rank));
    const int bg0 = (blockIdx.x >> 3) * BGR;

    const unsigned hb_u32   = (unsigned)__cvta_generic_to_shared(hbuf);
    const unsigned mbar_u32 = hb_u32 + 6144 * 4;   // two u64 after hbuf

    for (int m = tid; m < 6144; m += 256) hbuf[m] = 0.f;
    if (tid == 0) {
        asm volatile("mbarrier.init.shared.b64 [%0], 1;" :: "r"(mbar_u32) : "memory");
        asm volatile("mbarrier.init.shared.b64 [%0], 1;" :: "r"(mbar_u32 + 8) : "memory");
        asm volatile("mbarrier.arrive.expect_tx.shared.b64 _, [%0], 8192;"
                     :: "r"(mbar_u32) : "memory");
        asm volatile("mbarrier.arrive.expect_tx.shared.b64 _, [%0], 8192;"
                     :: "r"(mbar_u32 + 8) : "memory");
    }

    // load this lane's A fragments into registers, once
    unsigned avh[16][4], avl[16][4];
    {
        const unsigned* wh0 = g_WAh + (long)rank * 17920 + (warp * 16 + gq) * 140;
        const unsigned* wh1 = g_WAh + (long)rank * 17920 + (warp * 16 + gq + 8) * 140;
        const unsigned* wl0 = g_WAl + (long)rank * 17920 + (warp * 16 + gq) * 140;
        const unsigned* wl1 = g_WAl + (long)rank * 17920 + (warp * 16 + gq + 8) * 140;
        #pragma unroll
        for (int ks = 0; ks < 16; ++ks) {
            const int kp = ks * 8 + tg;
            avh[ks][0] = wh0[kp];     avh[ks][1] = wh1[kp];
            avh[ks][2] = wh0[kp + 4]; avh[ks][3] = wh1[kp + 4];
            avl[ks][0] = wl0[kp];     avl[ks][1] = wl1[kp];
            avl[ks][2] = wl0[kp + 4]; avl[ks][3] = wl1[kp + 4];
        }
    }

    // cell identity for this lane
    const int jl    = warp * 4 + (gq & 3);
    const int jg    = rank * 32 + jl;
    const int b     = 2 * tg + (gq >> 2);
    const int bglob = bg0 + b;

    // pre-map remote addresses (hoisted mapa)
    unsigned ra_h[CLU], ra_m[CLU];
    #pragma unroll
    for (int rr = 0; rr < CLU; ++rr) {
        asm volatile("mapa.shared::cluster.u32 %0, %1, %2;"
                     : "=r"(ra_h[rr]) : "r"(hb_u32), "r"(rr));
        asm volatile("mapa.shared::cluster.u32 %0, %1, %2;"
                     : "=r"(ra_m[rr]) : "r"(mbar_u32), "r"(rr));
    }

    float creg = 0.f, hreg = 0.f;
    float p0, p1, p2, p3;
    {
        const float* pp = PRE + (long)bglob * 1024 + jg;
        p0 = pp[0]; p1 = pp[256]; p2 = pp[512]; p3 = pp[768];
    }

    __syncthreads();
    CARRIVE(); CWAIT();   // mbarriers armed + buffers zeroed cluster-wide

    for (int t = 0; t < T_; ++t) {
        const int buf = t & 1;
        const unsigned bufn = buf ^ 1;

        if (t > 0) {
            unsigned phase = (unsigned)(((t - 1) >> 1) & 1);
            mbar_wait_clu(mbar_u32 + buf * 8, phase);
            if (tid == 0)
                asm volatile("mbarrier.arrive.expect_tx.shared.b64 _, [%0], 8192;"
                             :: "r"(mbar_u32 + buf * 8) : "memory");
        }

        const float* hp = hbuf + buf * 3072;

        float ahh[4] = {0.f, 0.f, 0.f, 0.f};
        float alh[4] = {0.f, 0.f, 0.f, 0.f};
        float ahl[4] = {0.f, 0.f, 0.f, 0.f};
        #pragma unroll
        for (int ks = 0; ks < 16; ++ks) {
            const int k0 = ks * 16 + tg * 2;
            float h00 = hp[(k0    ) * 12 + gq];
            float h01 = hp[(k0 + 1) * 12 + gq];
            float h10 = hp[(k0 + 8) * 12 + gq];
            float h11 = hp[(k0 + 9) * 12 + gq];
            unsigned b0h, b0l, b1h, b1l;
            split_bf2(h00, h01, b0h, b0l);
            split_bf2(h10, h11, b1h, b1l);
            unsigned bvh[2] = {b0h, b1h};
            unsigned bvl[2] = {b0l, b1l};
            MMA_BF16(ahh, avh[ks], bvh);
            MMA_BF16(alh, avl[ks], bvh);
            MMA_BF16(ahl, avh[ks], bvl);
        }
        float acc[4];
        #pragma unroll
        for (int q = 0; q < 4; ++q) acc[q] = ahh[q] + alh[q] + ahl[q];

        // pair gate owners: lane^16 flips gq bit2
        float r0 = __shfl_xor_sync(0xffffffffu, acc[0], 16);
        float r1 = __shfl_xor_sync(0xffffffffu, acc[1], 16);
        float r2 = __shfl_xor_sync(0xffffffffu, acc[2], 16);
        float r3 = __shfl_xor_sync(0xffffffffu, acc[3], 16);
        float s0, s1, s2, s3;
        if (gq < 4) { s0 = acc[0]; s1 = r0;     s2 = acc[2]; s3 = r2;     }
        else        { s0 = r1;     s1 = acc[1]; s2 = r3;     s3 = acc[3]; }

        float fg = sigf  (s0 + p0);
        float ig = sigf  (s1 + p1);
        float ug = tanhf_(s2 + p2);
        float og = sigf  (s3 + p3);
        creg = fg * creg + ig * ug;
        hreg = og * tanhf_(creg);
        out[((long)t * B_ + bglob) * H_ + jg] = hreg;

        // publish h via st.async (remote store + complete_tx on target mbar[bufn])
        const unsigned off = ((bufn * 256 + (unsigned)jg) * 12 + (unsigned)b) << 2;
        const unsigned mof = bufn * 8;
        const unsigned hv  = __float_as_uint(hreg);
        #pragma unroll
        for (int rr = 0; rr < CLU; ++rr) {
            asm volatile(
                "st.async.shared::cluster.mbarrier::complete_tx::bytes.b32 [%0], %1, [%2];"
                :: "r"(ra_h[rr] + off), "r"(hv), "r"(ra_m[rr] + mof) : "memory");
        }

        // prefetch next step's PRE
        int tn = (t < T_ - 1) ? t + 1 : t;
        const float* pq = PRE + ((long)tn * B_ + bglob) * 1024 + jg;
        p0 = pq[0]; p1 = pq[256]; p2 = pq[512]; p3 = pq[768];
    }

    out[(long)TB_ * H_ + bglob * H_ + jg] = hreg;                 // hx
    out[(long)TB_ * H_ + (long)B_ * H_ + bglob * H_ + jg] = creg; // cx

    CARRIVE(); CWAIT();   // keep cluster smem alive until all stores landed
}

// ---------------- launch ----------------
extern "C" void kernel_launch(void* const* d_in, const int* in_sizes, int n_in,
                              void* d_out, int out_size)
{
    const float* inputs = (const float*)d_in[0];
    const float* rot    = (const float*)d_in[1];
    const float* ent    = (const float*)d_in[2];
    const float* Wf = (const float*)d_in[3];  const float* bf = (const float*)d_in[4];
    const float* Wi = (const float*)d_in[5];  const float* bi = (const float*)d_in[6];
    const float* Wu = (const float*)d_in[7];  const float* bu = (const float*)d_in[8];
    const float* Wo = (const float*)d_in[9];  const float* bo = (const float*)d_in[10];
    const float* Wc = (const float*)d_in[11]; const float* bc = (const float*)d_in[12];
    float* out = (float*)d_out;

    float *Q, *K, *S, *CTX, *PRE, *Wall, *Wfold, *bfold;
    cudaGetSymbolAddress((void**)&Q,     g_Q);
    cudaGetSymbolAddress((void**)&K,     g_K);
    cudaGetSymbolAddress((void**)&S,     g_S);
    cudaGetSymbolAddress((void**)&CTX,   g_CTX);
    cudaGetSymbolAddress((void**)&PRE,   g_PRE);
    cudaGetSymbolAddress((void**)&Wall,  g_Wall);
    cudaGetSymbolAddress((void**)&Wfold, g_Wfold);
    cudaGetSymbolAddress((void**)&bfold, g_bfold);

    const int RSMEM = 6144 * 4 + 16;   // hbuf + 2 mbarriers
    cudaFuncSetAttribute(recur12_k, cudaFuncAttributeMaxDynamicSharedMemorySize, RSMEM);

    pack_init_k<<<256, 256>>>(Wf, Wi, Wu, Wo, bf, bi, bu, bo);
    bias_fold_k<<<128, 256>>>(bc);

    // Wfold[256:512] = Wc @ Wall[256:512]
    gemm_tc<false, false, false><<<dim3(1024 / 128, 256 / 128, 1), 256>>>(
        Wc, nullptr, Wall + 256 * 1024, Wfold + 256 * 1024, nullptr,
        256, 1024, 256, 256, 1024, 1024, 0, 0, 0);

    // Q = X @ rot ; K = X @ ent
    gemm_tc<false, false, false><<<dim3(E_ / 128, TB_ / 128, 1), 256>>>(
        inputs, nullptr, rot, Q, nullptr, TB_, E_, E_, E_, E_, E_, 0, 0, 0);
    gemm_tc<false, false, false><<<dim3(E_ / 128, TB_ / 128, 1), 256>>>(
        inputs, nullptr, ent, K, nullptr, TB_, E_, E_, E_, E_, E_, 0, 0, 0);

    // scores_b = Q_b @ K_b^T
    gemm_tc<true, false, false><<<dim3(T_ / 128, T_ / 128, B_), 256>>>(
        Q, nullptr, K, S, nullptr, T_, T_, E_, B_ * E_, B_ * E_, T_,
        (long)E_, (long)E_, (long)T_ * T_);

    softmax_k<<<B_ * T_, 128>>>(S);

    // context_b = S_b @ X_b
    gemm_tc<false, false, false><<<dim3(E_ / 128, T_ / 128, B_), 256>>>(
        S, nullptr, inputs, CTX, nullptr, T_, E_, T_, T_, B_ * E_, B_ * E_,
        (long)T_ * T_, (long)E_, (long)E_);

    // PRE = [X | CTX] @ Wfold + bfold
    gemm_tc<false, true, true><<<dim3(1024 / 128, TB_ / 128, 1), 256>>>(
        inputs, CTX, Wfold, PRE, bfold, TB_, 1024, 512, E_, 1024, 1024, 0, 0, 0);

    recur12_k<<<64, 256, RSMEM>>>(PRE, out);
    (void)in_sizes; (void)n_in; (void)out_size;
}